// round 8
// baseline (speedup 1.0000x reference)
#include <cuda_runtime.h>
#include <math.h>

#define PI_F 3.14159265358979323846f

// One block per batch image (128 blocks x 256 threads).
// The whole variational circuit (layer-0 U gates + layers 1..4 with CNOT rings)
// is data-independent: final_state = C * m, where m is a REAL 16-vector of
// cos/sin(pi*x) products (Rx phases (-i)^popc folded into C's columns) and C is
// a 16x16 complex matrix. 16 spare threads (t=196..211) build C in smem by
// evolving the 16 folded product-state columns; the 196 patch threads then do
// a complex-matrix x real-vector (512 FMA) + probs + <Z_q>. Then FC1/FC2.
__global__ __launch_bounds__(256, 1) void qnet_kernel(
    const float* __restrict__ x,      // [128,1,28,28]
    const float* __restrict__ weight, // [60]
    const float* __restrict__ fc1_w,  // [64,784]
    const float* __restrict__ fc1_b,  // [64]
    const float* __restrict__ fc2_w,  // [10,64]
    const float* __restrict__ fc2_b,  // [10]
    float* __restrict__ out)          // [128,10]
{
    __shared__ float4 ssu2[20];       // (ar, ai, br, bi) per (layer*4 + qubit)
    __shared__ float2 C2[16][16];     // C2[i][j] = (re, im) of C[i][j]
    __shared__ float sfeat[784];
    __shared__ float sh[64];

    const int t = threadIdx.x;
    const int b = blockIdx.x;

    // U = Ry(c)*Rz(bb)*Ry(a) = [[alpha, -conj(beta)],[beta, conj(alpha)]]
    if (t < 20) {
        const int layer = t >> 2, q = t & 3;
        const int base = layer * 12;
        float sa, ca, sb, cb, sc, cc;
        __sincosf(0.5f * weight[base + q],     &sa, &ca);
        __sincosf(0.5f * weight[base + 4 + q], &sb, &cb);
        __sincosf(0.5f * weight[base + 8 + q], &sc, &cc);
        const float ar =  cb * (cc * ca - sc * sa);
        const float ai = -sb * (cc * ca + sc * sa);
        const float br =  cb * (sc * ca + cc * sa);
        const float bi =  sb * (cc * sa - sc * ca);
        ssu2[t] = make_float4(ar, ai, br, bi);
    }

    // Patch threads: trig + partial products for m (independent of ssu2/C).
    float m01[4], m23[4];
    if (t < 196) {
        const int pi_ = t / 14, pj = t % 14;
        const float* xb = x + b * 784 + (2 * pi_) * 28 + 2 * pj;
        float c0, s0, c1, s1, c2, s2, c3, s3;
        __sincosf(PI_F * xb[0],  &s0, &c0);
        __sincosf(PI_F * xb[1],  &s1, &c1);
        __sincosf(PI_F * xb[28], &s2, &c2);
        __sincosf(PI_F * xb[29], &s3, &c3);
        m01[0] = c0 * c1; m01[1] = c0 * s1; m01[2] = s0 * c1; m01[3] = s0 * s1;
        m23[0] = c2 * c3; m23[1] = c2 * s3; m23[2] = s2 * c3; m23[3] = s2 * s3;
    }
    __syncthreads();   // ssu2 ready

    // Column threads: evolve folded column j of C through layers 1..4.
    if (t >= 196 && t < 212) {
        const int j = t - 196;

        // Per-qubit 2-vectors: column j_q of U_q times (-i)^{j_q} (phase folded).
        // j_q=0: v0=(x,y), v1=(z,w).  j_q=1: v0=(w,z), v1=(-y,-x).
        float v0r[4], v0i[4], v1r[4], v1i[4];
        #pragma unroll
        for (int q = 0; q < 4; q++) {
            const float4 u = ssu2[q];
            const int bit = (j >> (3 - q)) & 1;
            v0r[q] = bit ?  u.w : u.x;
            v0i[q] = bit ?  u.z : u.y;
            v1r[q] = bit ? -u.y : u.z;
            v1i[q] = bit ? -u.x : u.w;
        }

        // Product state via tree: w01 = v(q0) x v(q1), w23 = v(q2) x v(q3)
        float w01r[4], w01i[4], w23r[4], w23i[4];
        #pragma unroll
        for (int b0 = 0; b0 < 2; b0++) {
            const float x0r = b0 ? v1r[0] : v0r[0], x0i = b0 ? v1i[0] : v0i[0];
            const float y0r = b0 ? v1r[2] : v0r[2], y0i = b0 ? v1i[2] : v0i[2];
            #pragma unroll
            for (int b1 = 0; b1 < 2; b1++) {
                const float x1r = b1 ? v1r[1] : v0r[1], x1i = b1 ? v1i[1] : v0i[1];
                const float y1r = b1 ? v1r[3] : v0r[3], y1i = b1 ? v1i[3] : v0i[3];
                w01r[b0 * 2 + b1] = x0r * x1r - x0i * x1i;
                w01i[b0 * 2 + b1] = x0r * x1i + x0i * x1r;
                w23r[b0 * 2 + b1] = y0r * y1r - y0i * y1i;
                w23i[b0 * 2 + b1] = y0r * y1i + y0i * y1r;
            }
        }
        float ar[16], ai[16];
        #pragma unroll
        for (int i = 0; i < 16; i++) {
            const int hi = i >> 2, lo = i & 3;
            ar[i] = w01r[hi] * w23r[lo] - w01i[hi] * w23i[lo];
            ai[i] = w01r[hi] * w23i[lo] + w01i[hi] * w23r[lo];
        }

        // Layers 1..4: CNOT ring then merged SU(2) per qubit (proven R3 code).
        #pragma unroll
        for (int layer = 1; layer < 5; layer++) {
            #pragma unroll
            for (int q = 0; q < 4; q++) {
                const int cb = 8 >> q, tb = 8 >> ((q + 1) & 3);
                #pragma unroll
                for (int i = 0; i < 16; i++) {
                    if ((i & cb) && !(i & tb)) {
                        const int jj = i | tb;
                        float tr = ar[i]; ar[i] = ar[jj]; ar[jj] = tr;
                        float ti = ai[i]; ai[i] = ai[jj]; ai[jj] = ti;
                    }
                }
            }
            #pragma unroll
            for (int q = 0; q < 4; q++) {
                const float4 u = ssu2[layer * 4 + q];
                const int st = 8 >> q;
                #pragma unroll
                for (int i = 0; i < 16; i++) {
                    if (i & st) continue;
                    const int jj = i | st;
                    const float a0r = ar[i], a0i = ai[i], a1r = ar[jj], a1i = ai[jj];
                    ar[i]  = u.x * a0r - u.y * a0i - u.z * a1r - u.w * a1i;
                    ai[i]  = u.x * a0i + u.y * a0r - u.z * a1i + u.w * a1r;
                    ar[jj] = u.z * a0r - u.w * a0i + u.x * a1r + u.y * a1i;
                    ai[jj] = u.z * a0i + u.w * a0r + u.x * a1i - u.y * a1r;
                }
            }
        }

        #pragma unroll
        for (int i = 0; i < 16; i++) C2[i][j] = make_float2(ar[i], ai[i]);
    }
    __syncthreads();   // C ready

    if (t < 196) {
        // m[j] = m01[j>>2] * m23[j&3]  (real, phases live in C)
        float m[16];
        #pragma unroll
        for (int j = 0; j < 16; j++) m[j] = m01[j >> 2] * m23[j & 3];

        // out_i = sum_j C[i][j] * m[j];  p_i = |out_i|^2
        float p[16];
        #pragma unroll
        for (int i = 0; i < 16; i++) {
            const float4* crow = (const float4*)&C2[i][0];  // 2 complex per float4
            float accr = 0.f, acci = 0.f;
            #pragma unroll
            for (int jj = 0; jj < 8; jj++) {
                const float4 cc = crow[jj];
                accr += cc.x * m[2 * jj]     + cc.z * m[2 * jj + 1];
                acci += cc.y * m[2 * jj]     + cc.w * m[2 * jj + 1];
            }
            p[i] = accr * accr + acci * acci;
        }

        float e[4];
        #pragma unroll
        for (int q = 0; q < 4; q++) {
            const int st = 8 >> q;
            float acc = 0.f;
            #pragma unroll
            for (int i = 0; i < 16; i++) acc += (i & st) ? -p[i] : p[i];
            e[q] = acc;
        }
        *(float4*)&sfeat[t * 4] = make_float4(e[0], e[1], e[2], e[3]);
    }
    __syncthreads();

    // FC1: 64 outputs, each computed by 4 threads over 196-long k-slices (float4).
    {
        const int o = t >> 2, part = t & 3;
        const float4* wrow = (const float4*)(fc1_w + o * 784 + part * 196);
        const float4* frow = (const float4*)(sfeat + part * 196);
        float sum = 0.f;
        #pragma unroll 7
        for (int k = 0; k < 49; k++) {
            float4 w4 = wrow[k];
            float4 f4 = frow[k];
            sum += w4.x * f4.x + w4.y * f4.y + w4.z * f4.z + w4.w * f4.w;
        }
        sum += __shfl_xor_sync(0xffffffffu, sum, 1);
        sum += __shfl_xor_sync(0xffffffffu, sum, 2);
        if (part == 0) sh[o] = fmaxf(sum + fc1_b[o], 0.f);
    }
    __syncthreads();

    // FC2: 10 outputs
    if (t < 10) {
        float sum = fc2_b[t];
        const float* w2 = fc2_w + t * 64;
        #pragma unroll
        for (int k = 0; k < 64; k++) sum += w2[k] * sh[k];
        out[b * 10 + t] = sum;
    }
}

extern "C" void kernel_launch(void* const* d_in, const int* in_sizes, int n_in,
                              void* d_out, int out_size) {
    const float* x      = (const float*)d_in[0];
    const float* weight = (const float*)d_in[1];
    const float* fc1_w  = (const float*)d_in[2];
    const float* fc1_b  = (const float*)d_in[3];
    const float* fc2_w  = (const float*)d_in[4];
    const float* fc2_b  = (const float*)d_in[5];
    float* out = (float*)d_out;

    const int B = in_sizes[0] / 784;  // 128
    qnet_kernel<<<B, 256>>>(x, weight, fc1_w, fc1_b, fc2_w, fc2_b, out);
}

// round 9
// speedup vs baseline: 1.1404x; 1.1404x over previous
#include <cuda_runtime.h>
#include <math.h>

#define PI_F 3.14159265358979323846f

// One block per batch image (128 blocks x 256 threads).
// final_state = C * m:  m = REAL 16-vector of cos/sin(pi x) products (Rx
// phases folded into C), C = 16x16 complex circuit matrix (data-independent).
// Phase A: ALL 256 threads build C cooperatively -- thread (j=t>>4, i=t&15)
// evolves amplitude i of folded column j; gate partners via shfl.bfly within
// the 16-lane group. Phase B: 196 patch threads do trig + C*m + |.|^2 + <Z_q>.
// Then FC1 (relu) + FC2.
__global__ __launch_bounds__(256, 1) void qnet_kernel(
    const float* __restrict__ x,      // [128,1,28,28]
    const float* __restrict__ weight, // [60]
    const float* __restrict__ fc1_w,  // [64,784]
    const float* __restrict__ fc1_b,  // [64]
    const float* __restrict__ fc2_w,  // [10,64]
    const float* __restrict__ fc2_b,  // [10]
    float* __restrict__ out)          // [128,10]
{
    __shared__ float4 ssu2[20];       // (ar, ai, br, bi) per (layer*4 + qubit)
    __shared__ float2 C2[16][16];     // C2[i][j]
    __shared__ float sfeat[784];
    __shared__ float sh[64];

    const int t = threadIdx.x;
    const int b = blockIdx.x;

    // U = Ry(c)*Rz(bb)*Ry(a) = [[alpha, -conj(beta)],[beta, conj(alpha)]]
    if (t < 20) {
        const int layer = t >> 2, q = t & 3;
        const int base = layer * 12;
        float sa, ca, sb, cb, sc, cc;
        __sincosf(0.5f * weight[base + q],     &sa, &ca);
        __sincosf(0.5f * weight[base + 4 + q], &sb, &cb);
        __sincosf(0.5f * weight[base + 8 + q], &sc, &cc);
        ssu2[t] = make_float4( cb * (cc * ca - sc * sa),
                              -sb * (cc * ca + sc * sa),
                               cb * (sc * ca + cc * sa),
                               sb * (cc * sa - sc * ca));
    }

    // Issue patch x loads early; consumed after phase A (latency hidden).
    float px0, px1, px2, px3;
    if (t < 196) {
        const int pi_ = t / 14, pj = t % 14;
        const float* xb = x + b * 784 + (2 * pi_) * 28 + 2 * pj;
        px0 = xb[0]; px1 = xb[1]; px2 = xb[28]; px3 = xb[29];
    }
    __syncthreads();   // ssu2 ready

    // ---- Phase A: build C (all 256 threads, one amplitude each) ----
    {
        const int j = t >> 4;         // column
        const int i = t & 15;         // amplitude index (q0=bit3 .. q3=bit0)

        // Init: amp i of folded column j = prod_q w_q, where w_q is picked
        // from layer-0 U_q by (j_q, i_q); j_q=1 columns carry the (-i) fold.
        float arv = 1.f, aiv = 0.f;
        #pragma unroll
        for (int q = 0; q < 4; q++) {
            const float4 u = ssu2[q];
            const int jb = (j >> (3 - q)) & 1, ib = (i >> (3 - q)) & 1;
            float wr, wi;
            if (!jb) { wr = ib ?  u.z : u.x;  wi = ib ?  u.w : u.y; }
            else     { wr = ib ? -u.y : u.w;  wi = ib ? -u.x : u.z; }
            const float nr = arv * wr - aiv * wi;
            aiv = arv * wi + aiv * wr;
            arv = nr;
        }

        #pragma unroll
        for (int layer = 1; layer < 5; layer++) {
            // CNOT ring 0->1->2->3->0: conditional partner take
            #pragma unroll
            for (int q = 0; q < 4; q++) {
                const int cb = 8 >> q, tb = 8 >> ((q + 1) & 3);
                const float pr  = __shfl_xor_sync(0xffffffffu, arv, tb);
                const float pi2 = __shfl_xor_sync(0xffffffffu, aiv, tb);
                if (i & cb) { arv = pr; aiv = pi2; }
            }
            // Merged SU(2) per qubit: branch-free signed update
            #pragma unroll
            for (int q = 0; q < 4; q++) {
                const float4 u = ssu2[layer * 4 + q];
                const int st = 8 >> q;
                const float pr  = __shfl_xor_sync(0xffffffffu, arv, st);
                const float pi2 = __shfl_xor_sync(0xffffffffu, aiv, st);
                const bool hi = (i & st) != 0;
                const float ys = hi ? u.y : -u.y;
                const float zs = hi ? u.z : -u.z;
                const float nr = u.x * arv + ys * aiv + zs * pr  - u.w * pi2;
                const float ni = u.x * aiv - ys * arv + zs * pi2 + u.w * pr;
                arv = nr; aiv = ni;
            }
        }
        C2[i][j] = make_float2(arv, aiv);
    }
    __syncthreads();   // C ready

    // ---- Phase B: per-patch m vector + C*m + expectations ----
    if (t < 196) {
        float c0, s0, c1, s1, c2, s2, c3, s3;
        __sincosf(PI_F * px0, &s0, &c0);
        __sincosf(PI_F * px1, &s1, &c1);
        __sincosf(PI_F * px2, &s2, &c2);
        __sincosf(PI_F * px3, &s3, &c3);
        float m01[4], m23[4];
        m01[0] = c0 * c1; m01[1] = c0 * s1; m01[2] = s0 * c1; m01[3] = s0 * s1;
        m23[0] = c2 * c3; m23[1] = c2 * s3; m23[2] = s2 * c3; m23[3] = s2 * s3;
        float m[16];
        #pragma unroll
        for (int j = 0; j < 16; j++) m[j] = m01[j >> 2] * m23[j & 3];

        float p[16];
        #pragma unroll
        for (int i = 0; i < 16; i++) {
            const float4* crow = (const float4*)&C2[i][0];  // broadcast LDS.128
            float accr = 0.f, acci = 0.f;
            #pragma unroll
            for (int jj = 0; jj < 8; jj++) {
                const float4 cc = crow[jj];
                accr += cc.x * m[2 * jj] + cc.z * m[2 * jj + 1];
                acci += cc.y * m[2 * jj] + cc.w * m[2 * jj + 1];
            }
            p[i] = accr * accr + acci * acci;
        }

        float e[4];
        #pragma unroll
        for (int q = 0; q < 4; q++) {
            const int st = 8 >> q;
            float acc = 0.f;
            #pragma unroll
            for (int i = 0; i < 16; i++) acc += (i & st) ? -p[i] : p[i];
            e[q] = acc;
        }
        *(float4*)&sfeat[t * 4] = make_float4(e[0], e[1], e[2], e[3]);
    }
    __syncthreads();

    // FC1: 64 outputs, each computed by 4 threads over 196-long k-slices (float4).
    {
        const int o = t >> 2, part = t & 3;
        const float4* wrow = (const float4*)(fc1_w + o * 784 + part * 196);
        const float4* frow = (const float4*)(sfeat + part * 196);
        float sum = 0.f;
        #pragma unroll 7
        for (int k = 0; k < 49; k++) {
            float4 w4 = wrow[k];
            float4 f4 = frow[k];
            sum += w4.x * f4.x + w4.y * f4.y + w4.z * f4.z + w4.w * f4.w;
        }
        sum += __shfl_xor_sync(0xffffffffu, sum, 1);
        sum += __shfl_xor_sync(0xffffffffu, sum, 2);
        if (part == 0) sh[o] = fmaxf(sum + fc1_b[o], 0.f);
    }
    __syncthreads();

    // FC2: 10 outputs
    if (t < 10) {
        float sum = fc2_b[t];
        const float* w2 = fc2_w + t * 64;
        #pragma unroll
        for (int k = 0; k < 64; k++) sum += w2[k] * sh[k];
        out[b * 10 + t] = sum;
    }
}

extern "C" void kernel_launch(void* const* d_in, const int* in_sizes, int n_in,
                              void* d_out, int out_size) {
    const float* x      = (const float*)d_in[0];
    const float* weight = (const float*)d_in[1];
    const float* fc1_w  = (const float*)d_in[2];
    const float* fc1_b  = (const float*)d_in[3];
    const float* fc2_w  = (const float*)d_in[4];
    const float* fc2_b  = (const float*)d_in[5];
    float* out = (float*)d_out;

    const int B = in_sizes[0] / 784;  // 128
    qnet_kernel<<<B, 256>>>(x, weight, fc1_w, fc1_b, fc2_w, fc2_b, out);
}